// round 1
// baseline (speedup 1.0000x reference)
#include <cuda_runtime.h>
#include <math.h>

#define BB 2
#define NSEQ 2048
#define DD 1024
#define NH 16
#define HS 64
#define MM (BB*NSEQ)   // 4096 rows

// ---------------- scratch (allocation-free, __device__ globals) ----------------
__device__ float g_xn [MM*DD];        // LN1 output
__device__ float g_qkv[MM*3*DD];      // QKV
__device__ float g_oh [MM*DD];        // attention head outputs
__device__ float g_x1 [MM*DD];        // residual after attention
__device__ float g_xn2[MM*DD];        // LN2 output
__device__ float g_y  [MM*2*DD];      // MLP hidden

__device__ __forceinline__ float gelu_tanh(float x){
    float x3 = x*x*x;
    float t = tanhf(0.7978845608028654f * (x + 0.044715f*x3));
    return 0.5f*x*(1.0f+t);
}

// ---------------- LayerNorm: one block per row, 256 threads, float4 ----------------
__global__ __launch_bounds__(256) void ln_kernel(const float* __restrict__ x,
        const float* __restrict__ sc, const float* __restrict__ bi,
        float* __restrict__ out)
{
    const int row = blockIdx.x;
    const int t = threadIdx.x;
    const float4 v = ((const float4*)(x + (size_t)row*DD))[t];
    float s  = v.x+v.y+v.z+v.w;
    float sq = v.x*v.x+v.y*v.y+v.z*v.z+v.w*v.w;
    #pragma unroll
    for (int o=16;o>0;o>>=1){
        s  += __shfl_xor_sync(0xffffffffu,s ,o);
        sq += __shfl_xor_sync(0xffffffffu,sq,o);
    }
    __shared__ float ss[8], sqs[8];
    const int warp=t>>5, lane=t&31;
    if (lane==0){ ss[warp]=s; sqs[warp]=sq; }
    __syncthreads();
    if (t==0){
        float a=0.f,b=0.f;
        #pragma unroll
        for(int i=0;i<8;i++){a+=ss[i]; b+=sqs[i];}
        ss[0]=a; sqs[0]=b;
    }
    __syncthreads();
    const float mean = ss[0]*(1.0f/DD);
    const float var  = sqs[0]*(1.0f/DD) - mean*mean;
    const float inv  = rsqrtf(var + 1e-6f);
    const float4 sc4 = ((const float4*)sc)[t];
    const float4 bi4 = ((const float4*)bi)[t];
    float4 o4;
    o4.x = (v.x-mean)*inv*sc4.x + bi4.x;
    o4.y = (v.y-mean)*inv*sc4.y + bi4.y;
    o4.z = (v.z-mean)*inv*sc4.z + bi4.z;
    o4.w = (v.w-mean)*inv*sc4.w + bi4.w;
    ((float4*)(out + (size_t)row*DD))[t] = o4;
}

// ---------------- SGEMM 128x128x8, 256 threads, 8x8 per thread ----------------
// EPI: 0 = C=acc ; 1 = C=acc+bias[col]+res[idx] ; 2 = C=gelu(acc+bias[col])
template<int EPI>
__global__ __launch_bounds__(256) void sgemm_kernel(
    const float* __restrict__ A, const float* __restrict__ B,
    float* __restrict__ C, int M, int N, int K,
    const float* __restrict__ bias, const float* __restrict__ res)
{
    __shared__ float As[8][128];
    __shared__ float Bs[8][128];
    const int tid = threadIdx.x;
    const int tr = tid >> 4;          // 0..15 -> rows tr*8
    const int tc = tid & 15;          // 0..15 -> cols tc*8
    const int rowA = tid >> 1;        // 0..127
    const int colA = (tid & 1) << 2;  // 0 or 4
    const int rowB = tid >> 5;        // 0..7
    const int colB = (tid & 31) << 2; // 0..124

    const float* Ag = A + (size_t)(blockIdx.y*128 + rowA)*K + colA;
    const float* Bg = B + (size_t)rowB*N + blockIdx.x*128 + colB;

    float acc[8][8] = {};
    for (int k0=0;k0<K;k0+=8){
        const float4 a4 = *(const float4*)(Ag + k0);
        const float4 b4 = *(const float4*)(Bg + (size_t)k0*N);
        As[colA+0][rowA]=a4.x; As[colA+1][rowA]=a4.y;
        As[colA+2][rowA]=a4.z; As[colA+3][rowA]=a4.w;
        *(float4*)&Bs[rowB][colB] = b4;
        __syncthreads();
        #pragma unroll
        for(int k=0;k<8;k++){
            float ra[8], rb[8];
            *(float4*)&ra[0] = *(const float4*)&As[k][tr*8];
            *(float4*)&ra[4] = *(const float4*)&As[k][tr*8+4];
            *(float4*)&rb[0] = *(const float4*)&Bs[k][tc*8];
            *(float4*)&rb[4] = *(const float4*)&Bs[k][tc*8+4];
            #pragma unroll
            for(int i=0;i<8;i++)
                #pragma unroll
                for(int j=0;j<8;j++)
                    acc[i][j] = fmaf(ra[i], rb[j], acc[i][j]);
        }
        __syncthreads();
    }
    const int crow = blockIdx.y*128 + tr*8;
    const int ccol = blockIdx.x*128 + tc*8;
    #pragma unroll
    for(int i=0;i<8;i++){
        const size_t off = (size_t)(crow+i)*N + ccol;
        #pragma unroll
        for(int j0=0;j0<8;j0+=4){
            float vv[4];
            #pragma unroll
            for(int j=0;j<4;j++){
                float v = acc[i][j0+j];
                if (EPI==1) v += bias[ccol+j0+j] + res[off+j0+j];
                if (EPI==2) v = gelu_tanh(v + bias[ccol+j0+j]);
                vv[j]=v;
            }
            float4 o; o.x=vv[0]; o.y=vv[1]; o.z=vv[2]; o.w=vv[3];
            *(float4*)(C+off+j0) = o;
        }
    }
}

// ---------------- Causal flash attention, fp32 ----------------
// Block: 256 threads (16x16), BM=64 query rows, BKV=64 keys/tile.
// Shared: Qt[d][row] 16KB, KP (K transposed, reused for P) 16KB, Vs[key][d] 16KB = 48KB.
__global__ __launch_bounds__(256) void attn_kernel(const float* __restrict__ qkv,
                                                   float* __restrict__ oh)
{
    __shared__ float Qt[64*64];
    __shared__ float KP[64*64];
    __shared__ float Vs[64*64];
    const int qt = blockIdx.x;            // query tile 0..31
    const int bh = blockIdx.y;            // b*NH + h
    const int b = bh >> 4;
    const int h = bh & 15;
    const int tid = threadIdx.x;
    const int tx = tid & 15, ty = tid >> 4;
    const size_t base = (size_t)b * NSEQ * (3*DD);
    const int hoff = h*HS;

    // load Q tile transposed: Qt[d][row]
    for (int i = tid; i < 64*16; i += 256){
        const int row = i >> 4, d4 = (i & 15) << 2;
        const float4 q4 = *(const float4*)(qkv + base + (size_t)(qt*64+row)*(3*DD) + hoff + d4);
        Qt[(d4+0)*64+row]=q4.x; Qt[(d4+1)*64+row]=q4.y;
        Qt[(d4+2)*64+row]=q4.z; Qt[(d4+3)*64+row]=q4.w;
    }

    float o[4][4] = {};
    float m[4], l[4];
    #pragma unroll
    for(int r=0;r<4;r++){ m[r]=-1e30f; l[r]=0.f; }

    for (int jt = 0; jt <= qt; jt++){
        __syncthreads();
        // load K transposed into KP, V natural into Vs
        for (int i = tid; i < 64*16; i += 256){
            const int row = i >> 4, d4 = (i & 15) << 2;
            const size_t roff = base + (size_t)(jt*64+row)*(3*DD) + hoff + d4;
            const float4 k4 = *(const float4*)(qkv + roff + DD);
            KP[(d4+0)*64+row]=k4.x; KP[(d4+1)*64+row]=k4.y;
            KP[(d4+2)*64+row]=k4.z; KP[(d4+3)*64+row]=k4.w;
            const float4 v4 = *(const float4*)(qkv + roff + 2*DD);
            *(float4*)&Vs[row*64 + d4] = v4;
        }
        __syncthreads();

        // S = Q K^T (4x4 per thread) via outer product over d
        float s[4][4] = {};
        #pragma unroll 8
        for (int d=0; d<64; d++){
            const float4 q4 = *(const float4*)&Qt[d*64 + ty*4];
            const float4 k4 = *(const float4*)&KP[d*64 + tx*4];
            const float qv[4]={q4.x,q4.y,q4.z,q4.w};
            const float kv[4]={k4.x,k4.y,k4.z,k4.w};
            #pragma unroll
            for(int r=0;r<4;r++)
                #pragma unroll
                for(int c=0;c<4;c++)
                    s[r][c] = fmaf(qv[r], kv[c], s[r][c]);
        }
        __syncthreads();   // all threads done reading KP -> safe to reuse as P

        const int q0 = qt*64 + ty*4;
        const int k0 = jt*64 + tx*4;
        #pragma unroll
        for(int r=0;r<4;r++){
            float sv[4];
            #pragma unroll
            for(int c=0;c<4;c++){
                float v = s[r][c]*0.125f;           // 1/sqrt(64)
                if (k0+c > q0+r) v = -1e30f;        // causal mask
                sv[c]=v;
            }
            float rm = fmaxf(fmaxf(sv[0],sv[1]),fmaxf(sv[2],sv[3]));
            #pragma unroll
            for(int off=8;off>0;off>>=1) rm = fmaxf(rm, __shfl_xor_sync(0xffffffffu, rm, off));
            const float mn = fmaxf(m[r], rm);
            const float alpha = __expf(m[r]-mn);
            float p[4], rs=0.f;
            #pragma unroll
            for(int c=0;c<4;c++){ p[c]=__expf(sv[c]-mn); rs+=p[c]; }
            #pragma unroll
            for(int off=8;off>0;off>>=1) rs += __shfl_xor_sync(0xffffffffu, rs, off);
            l[r] = l[r]*alpha + rs;
            m[r] = mn;
            #pragma unroll
            for(int c=0;c<4;c++) o[r][c]*=alpha;
            #pragma unroll
            for(int c=0;c<4;c++) KP[(ty*4+r)*64 + tx*4+c] = p[c];
        }
        __syncthreads();

        // O += P @ V
        for (int kk=0; kk<64; kk++){
            float pv[4];
            #pragma unroll
            for(int r=0;r<4;r++) pv[r] = KP[(ty*4+r)*64 + kk];
            const float4 v4 = *(const float4*)&Vs[kk*64 + tx*4];
            #pragma unroll
            for(int r=0;r<4;r++){
                o[r][0] = fmaf(pv[r], v4.x, o[r][0]);
                o[r][1] = fmaf(pv[r], v4.y, o[r][1]);
                o[r][2] = fmaf(pv[r], v4.z, o[r][2]);
                o[r][3] = fmaf(pv[r], v4.w, o[r][3]);
            }
        }
    }

    // normalize + write
    #pragma unroll
    for(int r=0;r<4;r++){
        const float inv = 1.0f/l[r];
        float4 o4;
        o4.x=o[r][0]*inv; o4.y=o[r][1]*inv; o4.z=o[r][2]*inv; o4.w=o[r][3]*inv;
        *(float4*)(oh + (size_t)(b*NSEQ + qt*64 + ty*4 + r)*DD + hoff + tx*4) = o4;
    }
}

// ---------------- launch ----------------
extern "C" void kernel_launch(void* const* d_in, const int* in_sizes, int n_in,
                              void* d_out, int out_size)
{
    const float* x    = (const float*)d_in[0];
    const float* ln1s = (const float*)d_in[1];
    const float* ln1b = (const float*)d_in[2];
    const float* wqkv = (const float*)d_in[3];
    const float* wout = (const float*)d_in[4];
    const float* bout = (const float*)d_in[5];
    const float* ln2s = (const float*)d_in[6];
    const float* ln2b = (const float*)d_in[7];
    const float* w1   = (const float*)d_in[8];
    const float* b1   = (const float*)d_in[9];
    const float* w2   = (const float*)d_in[10];
    const float* b2   = (const float*)d_in[11];
    float* out = (float*)d_out;

    float *p_xn,*p_qkv,*p_oh,*p_x1,*p_xn2,*p_y;
    cudaGetSymbolAddress((void**)&p_xn , g_xn );
    cudaGetSymbolAddress((void**)&p_qkv, g_qkv);
    cudaGetSymbolAddress((void**)&p_oh , g_oh );
    cudaGetSymbolAddress((void**)&p_x1 , g_x1 );
    cudaGetSymbolAddress((void**)&p_xn2, g_xn2);
    cudaGetSymbolAddress((void**)&p_y  , g_y  );

    // LN1
    ln_kernel<<<MM,256>>>(x, ln1s, ln1b, p_xn);
    // QKV = xn @ w_qkv   [4096,1024]x[1024,3072]
    sgemm_kernel<0><<<dim3(3*DD/128, MM/128),256>>>(p_xn, wqkv, p_qkv, MM, 3*DD, DD, nullptr, nullptr);
    // causal attention
    attn_kernel<<<dim3(NSEQ/64, BB*NH),256>>>(p_qkv, p_oh);
    // x1 = oh @ w_out + b_out + x
    sgemm_kernel<1><<<dim3(DD/128, MM/128),256>>>(p_oh, wout, p_x1, MM, DD, DD, bout, x);
    // LN2
    ln_kernel<<<MM,256>>>(p_x1, ln2s, ln2b, p_xn2);
    // y = gelu(xn2 @ w1 + b1)   [4096,1024]x[1024,2048]
    sgemm_kernel<2><<<dim3(2*DD/128, MM/128),256>>>(p_xn2, w1, p_y, MM, 2*DD, DD, b1, nullptr);
    // out = y @ w2 + b2 + x1    [4096,2048]x[2048,1024]
    sgemm_kernel<1><<<dim3(DD/128, MM/128),256>>>(p_y, w2, out, MM, DD, 2*DD, b2, p_x1);
}

// round 2
// speedup vs baseline: 1.9491x; 1.9491x over previous
#include <cuda_runtime.h>
#include <math.h>
#include <stdint.h>

#define BB 2
#define NSEQ 2048
#define DD 1024
#define NH 16
#define HS 64
#define MM (BB*NSEQ)   // 4096 rows

// ---------------- scratch (allocation-free, __device__ globals) ----------------
__device__ float g_xn [MM*DD];        // LN1 output
__device__ float g_qkv[MM*3*DD];      // QKV
__device__ float g_oh [MM*DD];        // attention head outputs
__device__ float g_x1 [MM*DD];        // residual after attention
__device__ float g_xn2[MM*DD];        // LN2 output
__device__ float g_y  [MM*2*DD];      // MLP hidden

__device__ __forceinline__ float gelu_tanh(float x){
    // tanh-approx GELU with fast exp: tanh(u) = 1 - 2/(e^{2u}+1)
    float u = 0.7978845608028654f * (x + 0.044715f*x*x*x);
    float t = 1.0f - 2.0f/(__expf(2.0f*u)+1.0f);
    return 0.5f*x*(1.0f+t);
}

__device__ __forceinline__ uint32_t f2tf32(float x){
    uint32_t r;
    asm volatile("cvt.rna.tf32.f32 %0, %1;" : "=r"(r) : "f"(x));
    return r;
}

__device__ __forceinline__ void cp_async16(void* smem, const void* gmem){
    unsigned s = (unsigned)__cvta_generic_to_shared(smem);
    asm volatile("cp.async.cg.shared.global [%0], [%1], 16;" :: "r"(s), "l"(gmem));
}
__device__ __forceinline__ void cp_commit(){ asm volatile("cp.async.commit_group;"); }
template<int N> __device__ __forceinline__ void cp_wait(){ asm volatile("cp.async.wait_group %0;" :: "n"(N)); }

// ---------------- LayerNorm: one block per row, 256 threads, float4 ----------------
__global__ __launch_bounds__(256) void ln_kernel(const float* __restrict__ x,
        const float* __restrict__ sc, const float* __restrict__ bi,
        float* __restrict__ out)
{
    const int row = blockIdx.x;
    const int t = threadIdx.x;
    const float4 v = ((const float4*)(x + (size_t)row*DD))[t];
    float s  = v.x+v.y+v.z+v.w;
    float sq = v.x*v.x+v.y*v.y+v.z*v.z+v.w*v.w;
    #pragma unroll
    for (int o=16;o>0;o>>=1){
        s  += __shfl_xor_sync(0xffffffffu,s ,o);
        sq += __shfl_xor_sync(0xffffffffu,sq,o);
    }
    __shared__ float ss[8], sqs[8];
    const int warp=t>>5, lane=t&31;
    if (lane==0){ ss[warp]=s; sqs[warp]=sq; }
    __syncthreads();
    if (t==0){
        float a=0.f,b=0.f;
        #pragma unroll
        for(int i=0;i<8;i++){a+=ss[i]; b+=sqs[i];}
        ss[0]=a; sqs[0]=b;
    }
    __syncthreads();
    const float mean = ss[0]*(1.0f/DD);
    const float var  = sqs[0]*(1.0f/DD) - mean*mean;
    const float inv  = rsqrtf(var + 1e-6f);
    const float4 sc4 = ((const float4*)sc)[t];
    const float4 bi4 = ((const float4*)bi)[t];
    float4 o4;
    o4.x = (v.x-mean)*inv*sc4.x + bi4.x;
    o4.y = (v.y-mean)*inv*sc4.y + bi4.y;
    o4.z = (v.z-mean)*inv*sc4.z + bi4.z;
    o4.w = (v.w-mean)*inv*sc4.w + bi4.w;
    ((float4*)(out + (size_t)row*DD))[t] = o4;
}

// ---------------- TF32 tensor-core GEMM 128x128x16, 256 threads ----------------
// 8 warps in 4(m) x 2(n) grid; warp tile 32x64 = 2 m-frags x 8 n-frags of m16n8k8.
// A row-major [M,K], B row-major [K,N]. Double-buffered cp.async.
// EPI: 0 = C=acc ; 1 = C=acc+bias[col]+res ; 2 = C=gelu(acc+bias[col])
#define AS_STRIDE 20
#define BS_STRIDE 136
template<int EPI>
__global__ __launch_bounds__(256) void tgemm_kernel(
    const float* __restrict__ A, const float* __restrict__ B,
    float* __restrict__ C, int M, int N, int K,
    const float* __restrict__ bias, const float* __restrict__ res)
{
    __shared__ float As[2][128][AS_STRIDE];   // [m][k] layout
    __shared__ float Bs[2][16][BS_STRIDE];    // [k][n] layout

    const int tid  = threadIdx.x;
    const int lane = tid & 31;
    const int warp = tid >> 5;
    const int wm = warp >> 1;        // 0..3
    const int wn = warp & 1;         // 0..1
    const int mB = wm*32;
    const int nB = wn*64;
    const int bm = blockIdx.y*128;
    const int bn = blockIdx.x*128;

    // load indices
    const int ar  = tid >> 2;        // 0..63
    const int ac4 = (tid & 3) << 2;  // 0,4,8,12
    const int br  = tid >> 5;        // 0..7
    const int bc4 = (tid & 31) << 2; // 0..124

    const float* Ag0 = A + (size_t)(bm + ar     )*K + ac4;
    const float* Ag1 = A + (size_t)(bm + ar + 64)*K + ac4;
    const float* Bg0 = B + (size_t)(br    )*N + bn + bc4;
    const float* Bg1 = B + (size_t)(br + 8)*N + bn + bc4;

    const int nk = K >> 4;

    // prologue: stage 0
    cp_async16(&As[0][ar     ][ac4], Ag0);
    cp_async16(&As[0][ar + 64][ac4], Ag1);
    cp_async16(&Bs[0][br    ][bc4], Bg0);
    cp_async16(&Bs[0][br + 8][bc4], Bg1);
    cp_commit();

    float acc[2][8][4] = {};

    const int frow = lane >> 2;      // 0..7
    const int fcol = lane & 3;       // 0..3

    for (int kt = 0; kt < nk; kt++){
        const int cur = kt & 1;
        if (kt + 1 < nk){
            const int nxt = cur ^ 1;
            const int ko = (kt+1) << 4;
            cp_async16(&As[nxt][ar     ][ac4], Ag0 + ko);
            cp_async16(&As[nxt][ar + 64][ac4], Ag1 + ko);
            cp_async16(&Bs[nxt][br    ][bc4], Bg0 + (size_t)ko*N);
            cp_async16(&Bs[nxt][br + 8][bc4], Bg1 + (size_t)ko*N);
            cp_commit();
            cp_wait<1>();
        } else {
            cp_wait<0>();
        }
        __syncthreads();

        #pragma unroll
        for (int kk = 0; kk < 2; kk++){
            const int kc = kk*8 + fcol;
            uint32_t af[2][4], bf[8][2];
            #pragma unroll
            for (int i = 0; i < 2; i++){
                const int r0 = mB + i*16 + frow;
                af[i][0] = f2tf32(As[cur][r0    ][kc    ]);
                af[i][1] = f2tf32(As[cur][r0 + 8][kc    ]);
                af[i][2] = f2tf32(As[cur][r0    ][kc + 4]);
                af[i][3] = f2tf32(As[cur][r0 + 8][kc + 4]);
            }
            #pragma unroll
            for (int j = 0; j < 8; j++){
                const int n = nB + j*8 + frow;
                bf[j][0] = f2tf32(Bs[cur][kk*8 + fcol    ][n]);
                bf[j][1] = f2tf32(Bs[cur][kk*8 + fcol + 4][n]);
            }
            #pragma unroll
            for (int i = 0; i < 2; i++)
                #pragma unroll
                for (int j = 0; j < 8; j++){
                    asm volatile(
                        "mma.sync.aligned.m16n8k8.row.col.f32.tf32.tf32.f32 "
                        "{%0,%1,%2,%3},{%4,%5,%6,%7},{%8,%9},{%0,%1,%2,%3};"
                        : "+f"(acc[i][j][0]), "+f"(acc[i][j][1]),
                          "+f"(acc[i][j][2]), "+f"(acc[i][j][3])
                        : "r"(af[i][0]), "r"(af[i][1]), "r"(af[i][2]), "r"(af[i][3]),
                          "r"(bf[j][0]), "r"(bf[j][1]));
                }
        }
        __syncthreads();
    }

    // epilogue: c0,c1 at (row, col..col+1); c2,c3 at (row+8, col..col+1)
    #pragma unroll
    for (int i = 0; i < 2; i++){
        const int row = bm + mB + i*16 + frow;
        #pragma unroll
        for (int j = 0; j < 8; j++){
            const int col = bn + nB + j*8 + fcol*2;
            float v0 = acc[i][j][0], v1 = acc[i][j][1];
            float v2 = acc[i][j][2], v3 = acc[i][j][3];
            const size_t o0 = (size_t)row*N + col;
            const size_t o1 = (size_t)(row+8)*N + col;
            if (EPI == 1){
                const float b0 = bias[col], b1 = bias[col+1];
                v0 += b0 + res[o0];   v1 += b1 + res[o0+1];
                v2 += b0 + res[o1];   v3 += b1 + res[o1+1];
            } else if (EPI == 2){
                const float b0 = bias[col], b1 = bias[col+1];
                v0 = gelu_tanh(v0 + b0); v1 = gelu_tanh(v1 + b1);
                v2 = gelu_tanh(v2 + b0); v3 = gelu_tanh(v3 + b1);
            }
            *(float2*)(C + o0) = make_float2(v0, v1);
            *(float2*)(C + o1) = make_float2(v2, v3);
        }
    }
}

// ---------------- Causal flash attention, fp32 ----------------
__global__ __launch_bounds__(256) void attn_kernel(const float* __restrict__ qkv,
                                                   float* __restrict__ oh)
{
    __shared__ float Qt[64*64];
    __shared__ float KP[64*64];
    __shared__ float Vs[64*64];
    const int qt = blockIdx.x;
    const int bh = blockIdx.y;
    const int b = bh >> 4;
    const int h = bh & 15;
    const int tid = threadIdx.x;
    const int tx = tid & 15, ty = tid >> 4;
    const size_t base = (size_t)b * NSEQ * (3*DD);
    const int hoff = h*HS;

    for (int i = tid; i < 64*16; i += 256){
        const int row = i >> 4, d4 = (i & 15) << 2;
        const float4 q4 = *(const float4*)(qkv + base + (size_t)(qt*64+row)*(3*DD) + hoff + d4);
        Qt[(d4+0)*64+row]=q4.x; Qt[(d4+1)*64+row]=q4.y;
        Qt[(d4+2)*64+row]=q4.z; Qt[(d4+3)*64+row]=q4.w;
    }

    float o[4][4] = {};
    float m[4], l[4];
    #pragma unroll
    for(int r=0;r<4;r++){ m[r]=-1e30f; l[r]=0.f; }

    for (int jt = 0; jt <= qt; jt++){
        __syncthreads();
        for (int i = tid; i < 64*16; i += 256){
            const int row = i >> 4, d4 = (i & 15) << 2;
            const size_t roff = base + (size_t)(jt*64+row)*(3*DD) + hoff + d4;
            const float4 k4 = *(const float4*)(qkv + roff + DD);
            KP[(d4+0)*64+row]=k4.x; KP[(d4+1)*64+row]=k4.y;
            KP[(d4+2)*64+row]=k4.z; KP[(d4+3)*64+row]=k4.w;
            const float4 v4 = *(const float4*)(qkv + roff + 2*DD);
            *(float4*)&Vs[row*64 + d4] = v4;
        }
        __syncthreads();

        float s[4][4] = {};
        #pragma unroll 8
        for (int d=0; d<64; d++){
            const float4 q4 = *(const float4*)&Qt[d*64 + ty*4];
            const float4 k4 = *(const float4*)&KP[d*64 + tx*4];
            const float qv[4]={q4.x,q4.y,q4.z,q4.w};
            const float kv[4]={k4.x,k4.y,k4.z,k4.w};
            #pragma unroll
            for(int r=0;r<4;r++)
                #pragma unroll
                for(int c=0;c<4;c++)
                    s[r][c] = fmaf(qv[r], kv[c], s[r][c]);
        }
        __syncthreads();

        const int q0 = qt*64 + ty*4;
        const int k0 = jt*64 + tx*4;
        #pragma unroll
        for(int r=0;r<4;r++){
            float sv[4];
            #pragma unroll
            for(int c=0;c<4;c++){
                float v = s[r][c]*0.125f;
                if (k0+c > q0+r) v = -1e30f;
                sv[c]=v;
            }
            float rm = fmaxf(fmaxf(sv[0],sv[1]),fmaxf(sv[2],sv[3]));
            #pragma unroll
            for(int off=8;off>0;off>>=1) rm = fmaxf(rm, __shfl_xor_sync(0xffffffffu, rm, off));
            const float mn = fmaxf(m[r], rm);
            const float alpha = __expf(m[r]-mn);
            float p[4], rs=0.f;
            #pragma unroll
            for(int c=0;c<4;c++){ p[c]=__expf(sv[c]-mn); rs+=p[c]; }
            #pragma unroll
            for(int off=8;off>0;off>>=1) rs += __shfl_xor_sync(0xffffffffu, rs, off);
            l[r] = l[r]*alpha + rs;
            m[r] = mn;
            #pragma unroll
            for(int c=0;c<4;c++) o[r][c]*=alpha;
            #pragma unroll
            for(int c=0;c<4;c++) KP[(ty*4+r)*64 + tx*4+c] = p[c];
        }
        __syncthreads();

        for (int kk=0; kk<64; kk++){
            float pv[4];
            #pragma unroll
            for(int r=0;r<4;r++) pv[r] = KP[(ty*4+r)*64 + kk];
            const float4 v4 = *(const float4*)&Vs[kk*64 + tx*4];
            #pragma unroll
            for(int r=0;r<4;r++){
                o[r][0] = fmaf(pv[r], v4.x, o[r][0]);
                o[r][1] = fmaf(pv[r], v4.y, o[r][1]);
                o[r][2] = fmaf(pv[r], v4.z, o[r][2]);
                o[r][3] = fmaf(pv[r], v4.w, o[r][3]);
            }
        }
    }

    #pragma unroll
    for(int r=0;r<4;r++){
        const float inv = 1.0f/l[r];
        float4 o4;
        o4.x=o[r][0]*inv; o4.y=o[r][1]*inv; o4.z=o[r][2]*inv; o4.w=o[r][3]*inv;
        *(float4*)(oh + (size_t)(b*NSEQ + qt*64 + ty*4 + r)*DD + hoff + tx*4) = o4;
    }
}

// ---------------- launch ----------------
extern "C" void kernel_launch(void* const* d_in, const int* in_sizes, int n_in,
                              void* d_out, int out_size)
{
    const float* x    = (const float*)d_in[0];
    const float* ln1s = (const float*)d_in[1];
    const float* ln1b = (const float*)d_in[2];
    const float* wqkv = (const float*)d_in[3];
    const float* wout = (const float*)d_in[4];
    const float* bout = (const float*)d_in[5];
    const float* ln2s = (const float*)d_in[6];
    const float* ln2b = (const float*)d_in[7];
    const float* w1   = (const float*)d_in[8];
    const float* b1   = (const float*)d_in[9];
    const float* w2   = (const float*)d_in[10];
    const float* b2   = (const float*)d_in[11];
    float* out = (float*)d_out;

    float *p_xn,*p_qkv,*p_oh,*p_x1,*p_xn2,*p_y;
    cudaGetSymbolAddress((void**)&p_xn , g_xn );
    cudaGetSymbolAddress((void**)&p_qkv, g_qkv);
    cudaGetSymbolAddress((void**)&p_oh , g_oh );
    cudaGetSymbolAddress((void**)&p_x1 , g_x1 );
    cudaGetSymbolAddress((void**)&p_xn2, g_xn2);
    cudaGetSymbolAddress((void**)&p_y  , g_y  );

    // LN1
    ln_kernel<<<MM,256>>>(x, ln1s, ln1b, p_xn);
    // QKV = xn @ w_qkv   [4096,1024]x[1024,3072]
    tgemm_kernel<0><<<dim3(3*DD/128, MM/128),256>>>(p_xn, wqkv, p_qkv, MM, 3*DD, DD, nullptr, nullptr);
    // causal attention
    attn_kernel<<<dim3(NSEQ/64, BB*NH),256>>>(p_qkv, p_oh);
    // x1 = oh @ w_out + b_out + x
    tgemm_kernel<1><<<dim3(DD/128, MM/128),256>>>(p_oh, wout, p_x1, MM, DD, DD, bout, x);
    // LN2
    ln_kernel<<<MM,256>>>(p_x1, ln2s, ln2b, p_xn2);
    // y = gelu(xn2 @ w1 + b1)   [4096,1024]x[1024,2048]
    tgemm_kernel<2><<<dim3(2*DD/128, MM/128),256>>>(p_xn2, w1, p_y, MM, 2*DD, DD, b1, nullptr);
    // out = y @ w2 + b2 + x1    [4096,2048]x[2048,1024]
    tgemm_kernel<1><<<dim3(DD/128, MM/128),256>>>(p_y, w2, out, MM, DD, 2*DD, b2, p_x1);
}

// round 3
// speedup vs baseline: 3.0194x; 1.5491x over previous
#include <cuda_runtime.h>
#include <math.h>
#include <stdint.h>

#define BB 2
#define NSEQ 2048
#define DD 1024
#define NH 16
#define HS 64
#define MM (BB*NSEQ)   // 4096 rows

// ---------------- scratch (allocation-free, __device__ globals) ----------------
__device__ float g_xn [MM*DD];        // LN1 output
__device__ float g_qkv[MM*3*DD];      // QKV
__device__ float g_oh [MM*DD];        // attention head outputs
__device__ float g_x1 [MM*DD];        // residual after attention
__device__ float g_xn2[MM*DD];        // LN2 output
__device__ float g_y  [MM*2*DD];      // MLP hidden

__device__ __forceinline__ float gelu_tanh(float x){
    float u = 0.7978845608028654f * (x + 0.044715f*x*x*x);
    float t = 1.0f - 2.0f/(__expf(2.0f*u)+1.0f);
    return 0.5f*x*(1.0f+t);
}

__device__ __forceinline__ uint32_t f2tf32(float x){
    uint32_t r;
    asm volatile("cvt.rna.tf32.f32 %0, %1;" : "=r"(r) : "f"(x));
    return r;
}

__device__ __forceinline__ void cp_async16(void* smem, const void* gmem){
    unsigned s = (unsigned)__cvta_generic_to_shared(smem);
    asm volatile("cp.async.cg.shared.global [%0], [%1], 16;" :: "r"(s), "l"(gmem));
}
__device__ __forceinline__ void cp_commit(){ asm volatile("cp.async.commit_group;"); }
template<int N> __device__ __forceinline__ void cp_wait(){ asm volatile("cp.async.wait_group %0;" :: "n"(N)); }

__device__ __forceinline__ void mma_tf32(float c[4], uint32_t a0, uint32_t a1,
                                         uint32_t a2, uint32_t a3,
                                         uint32_t b0, uint32_t b1){
    asm volatile(
        "mma.sync.aligned.m16n8k8.row.col.f32.tf32.tf32.f32 "
        "{%0,%1,%2,%3},{%4,%5,%6,%7},{%8,%9},{%0,%1,%2,%3};"
        : "+f"(c[0]), "+f"(c[1]), "+f"(c[2]), "+f"(c[3])
        : "r"(a0), "r"(a1), "r"(a2), "r"(a3), "r"(b0), "r"(b1));
}

// ---------------- LayerNorm: one block per row, 256 threads, float4 ----------------
__global__ __launch_bounds__(256) void ln_kernel(const float* __restrict__ x,
        const float* __restrict__ sc, const float* __restrict__ bi,
        float* __restrict__ out)
{
    const int row = blockIdx.x;
    const int t = threadIdx.x;
    const float4 v = ((const float4*)(x + (size_t)row*DD))[t];
    float s  = v.x+v.y+v.z+v.w;
    float sq = v.x*v.x+v.y*v.y+v.z*v.z+v.w*v.w;
    #pragma unroll
    for (int o=16;o>0;o>>=1){
        s  += __shfl_xor_sync(0xffffffffu,s ,o);
        sq += __shfl_xor_sync(0xffffffffu,sq,o);
    }
    __shared__ float ss[8], sqs[8];
    const int warp=t>>5, lane=t&31;
    if (lane==0){ ss[warp]=s; sqs[warp]=sq; }
    __syncthreads();
    if (t==0){
        float a=0.f,b=0.f;
        #pragma unroll
        for(int i=0;i<8;i++){a+=ss[i]; b+=sqs[i];}
        ss[0]=a; sqs[0]=b;
    }
    __syncthreads();
    const float mean = ss[0]*(1.0f/DD);
    const float var  = sqs[0]*(1.0f/DD) - mean*mean;
    const float inv  = rsqrtf(var + 1e-6f);
    const float4 sc4 = ((const float4*)sc)[t];
    const float4 bi4 = ((const float4*)bi)[t];
    float4 o4;
    o4.x = (v.x-mean)*inv*sc4.x + bi4.x;
    o4.y = (v.y-mean)*inv*sc4.y + bi4.y;
    o4.z = (v.z-mean)*inv*sc4.z + bi4.z;
    o4.w = (v.w-mean)*inv*sc4.w + bi4.w;
    ((float4*)(out + (size_t)row*DD))[t] = o4;
}

// ---------------- TF32 tensor-core GEMM 128x128x16, 256 threads ----------------
#define AS_STRIDE 20
#define BS_STRIDE 136
template<int EPI>
__global__ __launch_bounds__(256) void tgemm_kernel(
    const float* __restrict__ A, const float* __restrict__ B,
    float* __restrict__ C, int M, int N, int K,
    const float* __restrict__ bias, const float* __restrict__ res)
{
    __shared__ float As[2][128][AS_STRIDE];
    __shared__ float Bs[2][16][BS_STRIDE];

    const int tid  = threadIdx.x;
    const int lane = tid & 31;
    const int warp = tid >> 5;
    const int wm = warp >> 1;
    const int wn = warp & 1;
    const int mB = wm*32;
    const int nB = wn*64;
    const int bm = blockIdx.y*128;
    const int bn = blockIdx.x*128;

    const int ar  = tid >> 2;
    const int ac4 = (tid & 3) << 2;
    const int br  = tid >> 5;
    const int bc4 = (tid & 31) << 2;

    const float* Ag0 = A + (size_t)(bm + ar     )*K + ac4;
    const float* Ag1 = A + (size_t)(bm + ar + 64)*K + ac4;
    const float* Bg0 = B + (size_t)(br    )*N + bn + bc4;
    const float* Bg1 = B + (size_t)(br + 8)*N + bn + bc4;

    const int nk = K >> 4;

    cp_async16(&As[0][ar     ][ac4], Ag0);
    cp_async16(&As[0][ar + 64][ac4], Ag1);
    cp_async16(&Bs[0][br    ][bc4], Bg0);
    cp_async16(&Bs[0][br + 8][bc4], Bg1);
    cp_commit();

    float acc[2][8][4] = {};

    const int frow = lane >> 2;
    const int fcol = lane & 3;

    for (int kt = 0; kt < nk; kt++){
        const int cur = kt & 1;
        if (kt + 1 < nk){
            const int nxt = cur ^ 1;
            const int ko = (kt+1) << 4;
            cp_async16(&As[nxt][ar     ][ac4], Ag0 + ko);
            cp_async16(&As[nxt][ar + 64][ac4], Ag1 + ko);
            cp_async16(&Bs[nxt][br    ][bc4], Bg0 + (size_t)ko*N);
            cp_async16(&Bs[nxt][br + 8][bc4], Bg1 + (size_t)ko*N);
            cp_commit();
            cp_wait<1>();
        } else {
            cp_wait<0>();
        }
        __syncthreads();

        #pragma unroll
        for (int kk = 0; kk < 2; kk++){
            const int kc = kk*8 + fcol;
            uint32_t af[2][4], bf[8][2];
            #pragma unroll
            for (int i = 0; i < 2; i++){
                const int r0 = mB + i*16 + frow;
                af[i][0] = f2tf32(As[cur][r0    ][kc    ]);
                af[i][1] = f2tf32(As[cur][r0 + 8][kc    ]);
                af[i][2] = f2tf32(As[cur][r0    ][kc + 4]);
                af[i][3] = f2tf32(As[cur][r0 + 8][kc + 4]);
            }
            #pragma unroll
            for (int j = 0; j < 8; j++){
                const int n = nB + j*8 + frow;
                bf[j][0] = f2tf32(Bs[cur][kk*8 + fcol    ][n]);
                bf[j][1] = f2tf32(Bs[cur][kk*8 + fcol + 4][n]);
            }
            #pragma unroll
            for (int i = 0; i < 2; i++)
                #pragma unroll
                for (int j = 0; j < 8; j++)
                    mma_tf32(acc[i][j], af[i][0], af[i][1], af[i][2], af[i][3],
                             bf[j][0], bf[j][1]);
        }
        __syncthreads();
    }

    #pragma unroll
    for (int i = 0; i < 2; i++){
        const int row = bm + mB + i*16 + frow;
        #pragma unroll
        for (int j = 0; j < 8; j++){
            const int col = bn + nB + j*8 + fcol*2;
            float v0 = acc[i][j][0], v1 = acc[i][j][1];
            float v2 = acc[i][j][2], v3 = acc[i][j][3];
            const size_t o0 = (size_t)row*N + col;
            const size_t o1 = (size_t)(row+8)*N + col;
            if (EPI == 1){
                const float b0 = bias[col], b1 = bias[col+1];
                v0 += b0 + res[o0];   v1 += b1 + res[o0+1];
                v2 += b0 + res[o1];   v3 += b1 + res[o1+1];
            } else if (EPI == 2){
                const float b0 = bias[col], b1 = bias[col+1];
                v0 = gelu_tanh(v0 + b0); v1 = gelu_tanh(v1 + b1);
                v2 = gelu_tanh(v2 + b0); v3 = gelu_tanh(v3 + b1);
            }
            *(float2*)(C + o0) = make_float2(v0, v1);
            *(float2*)(C + o1) = make_float2(v2, v3);
        }
    }
}

// ---------------- Causal flash attention on tensor cores (tf32) ----------------
// 128 threads = 4 warps; warp w owns query rows [w*16, w*16+16) of a 64-row tile.
// Row softmax stats are warp-local (4-lane shfl). KP buffer holds K then P.
// Vt holds V transposed [d][key] for the PV B-operand.
#define ATS 68    // smem row stride (64 + 4 pad -> conflict-free fragment access)
__global__ __launch_bounds__(128, 3) void attn_tc_kernel(const float* __restrict__ qkv,
                                                         float* __restrict__ oh)
{
    extern __shared__ float sm[];
    float* Qs = sm;                 // [64][ATS]  Q[row][d]
    float* KP = sm + 64*ATS;        // [64][ATS]  K[key][d], then P[row][key]
    float* Vt = sm + 2*64*ATS;      // [64][ATS]  V^T[d][key]

    const int qt = gridDim.x - 1 - blockIdx.x;   // heavy tiles first
    const int bh = blockIdx.y;
    const int b = bh >> 4;
    const int h = bh & 15;
    const int tid = threadIdx.x;
    const int lane = tid & 31;
    const int warp = tid >> 5;
    const int mB = warp * 16;
    const int g = lane >> 2;        // 0..7  (fragment row group)
    const int c = lane & 3;         // 0..3  (fragment col group)
    const size_t base = (size_t)b * NSEQ * (3*DD);
    const int hoff = h * HS;

    // load Q tile
    for (int i = tid; i < 64*16; i += 128){
        const int row = i >> 4, d4 = (i & 15) << 2;
        const float4 q4 = *(const float4*)(qkv + base + (size_t)(qt*64+row)*(3*DD) + hoff + d4);
        *(float4*)&Qs[row*ATS + d4] = q4;
    }
    __syncthreads();

    // hoist Q fragments (reused for every KV tile)
    uint32_t qa[8][4];
    #pragma unroll
    for (int kk = 0; kk < 8; kk++){
        qa[kk][0] = f2tf32(Qs[(mB+g  )*ATS + kk*8 + c    ]);
        qa[kk][1] = f2tf32(Qs[(mB+g+8)*ATS + kk*8 + c    ]);
        qa[kk][2] = f2tf32(Qs[(mB+g  )*ATS + kk*8 + c + 4]);
        qa[kk][3] = f2tf32(Qs[(mB+g+8)*ATS + kk*8 + c + 4]);
    }

    float o[8][4] = {};
    float m0=-1e30f, m1=-1e30f, l0=0.f, l1=0.f;

    const int r0g = qt*64 + mB + g;      // global query row for c0/c1
    const int r1g = r0g + 8;             // for c2/c3

    for (int jt = 0; jt <= qt; jt++){
        __syncthreads();     // prev iteration's PV reads of KP/Vt complete
        for (int i = tid; i < 64*16; i += 128){
            const int row = i >> 4, d4 = (i & 15) << 2;
            const size_t roff = base + (size_t)(jt*64+row)*(3*DD) + hoff + d4;
            const float4 k4 = *(const float4*)(qkv + roff + DD);
            *(float4*)&KP[row*ATS + d4] = k4;
            const float4 v4 = *(const float4*)(qkv + roff + 2*DD);
            Vt[(d4+0)*ATS+row]=v4.x; Vt[(d4+1)*ATS+row]=v4.y;
            Vt[(d4+2)*ATS+row]=v4.z; Vt[(d4+3)*ATS+row]=v4.w;
        }
        __syncthreads();

        // S = Q K^T  (warp: 16 x 64)
        float s[8][4] = {};
        #pragma unroll
        for (int kk = 0; kk < 8; kk++){
            #pragma unroll
            for (int j = 0; j < 8; j++){
                const uint32_t b0 = f2tf32(KP[(j*8+g)*ATS + kk*8 + c    ]);
                const uint32_t b1 = f2tf32(KP[(j*8+g)*ATS + kk*8 + c + 4]);
                mma_tf32(s[j], qa[kk][0], qa[kk][1], qa[kk][2], qa[kk][3], b0, b1);
            }
        }
        __syncthreads();     // all warps finished reading KP(K); safe to write P

        // scale + causal mask + row max
        float rm0 = -1e30f, rm1 = -1e30f;
        #pragma unroll
        for (int j = 0; j < 8; j++){
            const int col = jt*64 + j*8 + 2*c;
            #pragma unroll
            for (int t2 = 0; t2 < 2; t2++){
                float v0 = s[j][t2]*0.125f;
                float v1 = s[j][2+t2]*0.125f;
                if (jt == qt){
                    if (col+t2 > r0g) v0 = -1e30f;
                    if (col+t2 > r1g) v1 = -1e30f;
                }
                s[j][t2] = v0;  s[j][2+t2] = v1;
                rm0 = fmaxf(rm0, v0); rm1 = fmaxf(rm1, v1);
            }
        }
        #pragma unroll
        for (int off = 1; off <= 2; off <<= 1){
            rm0 = fmaxf(rm0, __shfl_xor_sync(0xffffffffu, rm0, off));
            rm1 = fmaxf(rm1, __shfl_xor_sync(0xffffffffu, rm1, off));
        }
        const float mn0 = fmaxf(m0, rm0), mn1 = fmaxf(m1, rm1);
        const float alpha0 = __expf(m0 - mn0), alpha1 = __expf(m1 - mn1);
        m0 = mn0; m1 = mn1;

        // P = exp(S - m), row sums, store P to KP
        float rs0 = 0.f, rs1 = 0.f;
        #pragma unroll
        for (int j = 0; j < 8; j++){
            float p0 = __expf(s[j][0] - mn0);
            float p1 = __expf(s[j][1] - mn0);
            float p2 = __expf(s[j][2] - mn1);
            float p3 = __expf(s[j][3] - mn1);
            rs0 += p0 + p1;  rs1 += p2 + p3;
            *(float2*)&KP[(mB+g  )*ATS + j*8 + 2*c] = make_float2(p0, p1);
            *(float2*)&KP[(mB+g+8)*ATS + j*8 + 2*c] = make_float2(p2, p3);
        }
        #pragma unroll
        for (int off = 1; off <= 2; off <<= 1){
            rs0 += __shfl_xor_sync(0xffffffffu, rs0, off);
            rs1 += __shfl_xor_sync(0xffffffffu, rs1, off);
        }
        l0 = l0*alpha0 + rs0;
        l1 = l1*alpha1 + rs1;

        // rescale O accumulators
        #pragma unroll
        for (int j = 0; j < 8; j++){
            o[j][0] *= alpha0; o[j][1] *= alpha0;
            o[j][2] *= alpha1; o[j][3] *= alpha1;
        }
        __syncwarp();

        // O += P @ V  (A = own P rows from KP, B = Vt)
        #pragma unroll
        for (int kk = 0; kk < 8; kk++){
            const uint32_t a0 = f2tf32(KP[(mB+g  )*ATS + kk*8 + c    ]);
            const uint32_t a1 = f2tf32(KP[(mB+g+8)*ATS + kk*8 + c    ]);
            const uint32_t a2 = f2tf32(KP[(mB+g  )*ATS + kk*8 + c + 4]);
            const uint32_t a3 = f2tf32(KP[(mB+g+8)*ATS + kk*8 + c + 4]);
            #pragma unroll
            for (int j = 0; j < 8; j++){
                const uint32_t b0 = f2tf32(Vt[(j*8+g)*ATS + kk*8 + c    ]);
                const uint32_t b1 = f2tf32(Vt[(j*8+g)*ATS + kk*8 + c + 4]);
                mma_tf32(o[j], a0, a1, a2, a3, b0, b1);
            }
        }
    }

    // normalize + write: row r0g gets c0,c1 ; row r1g gets c2,c3
    const float inv0 = 1.0f/l0, inv1 = 1.0f/l1;
    #pragma unroll
    for (int j = 0; j < 8; j++){
        const int col = hoff + j*8 + 2*c;
        float* p0 = oh + (size_t)(b*NSEQ + r0g)*DD + col;
        float* p1 = oh + (size_t)(b*NSEQ + r1g)*DD + col;
        *(float2*)p0 = make_float2(o[j][0]*inv0, o[j][1]*inv0);
        *(float2*)p1 = make_float2(o[j][2]*inv1, o[j][3]*inv1);
    }
}

// ---------------- launch ----------------
extern "C" void kernel_launch(void* const* d_in, const int* in_sizes, int n_in,
                              void* d_out, int out_size)
{
    const float* x    = (const float*)d_in[0];
    const float* ln1s = (const float*)d_in[1];
    const float* ln1b = (const float*)d_in[2];
    const float* wqkv = (const float*)d_in[3];
    const float* wout = (const float*)d_in[4];
    const float* bout = (const float*)d_in[5];
    const float* ln2s = (const float*)d_in[6];
    const float* ln2b = (const float*)d_in[7];
    const float* w1   = (const float*)d_in[8];
    const float* b1   = (const float*)d_in[9];
    const float* w2   = (const float*)d_in[10];
    const float* b2   = (const float*)d_in[11];
    float* out = (float*)d_out;

    float *p_xn,*p_qkv,*p_oh,*p_x1,*p_xn2,*p_y;
    cudaGetSymbolAddress((void**)&p_xn , g_xn );
    cudaGetSymbolAddress((void**)&p_qkv, g_qkv);
    cudaGetSymbolAddress((void**)&p_oh , g_oh );
    cudaGetSymbolAddress((void**)&p_x1 , g_x1 );
    cudaGetSymbolAddress((void**)&p_xn2, g_xn2);
    cudaGetSymbolAddress((void**)&p_y  , g_y  );

    const int attn_smem = 3*64*ATS*sizeof(float);   // 52224 B
    cudaFuncSetAttribute(attn_tc_kernel, cudaFuncAttributeMaxDynamicSharedMemorySize, attn_smem);

    // LN1
    ln_kernel<<<MM,256>>>(x, ln1s, ln1b, p_xn);
    // QKV = xn @ w_qkv   [4096,1024]x[1024,3072]
    tgemm_kernel<0><<<dim3(3*DD/128, MM/128),256>>>(p_xn, wqkv, p_qkv, MM, 3*DD, DD, nullptr, nullptr);
    // causal attention (tensor cores)
    attn_tc_kernel<<<dim3(NSEQ/64, BB*NH),128,attn_smem>>>(p_qkv, p_oh);
    // x1 = oh @ w_out + b_out + x
    tgemm_kernel<1><<<dim3(DD/128, MM/128),256>>>(p_oh, wout, p_x1, MM, DD, DD, bout, x);
    // LN2
    ln_kernel<<<MM,256>>>(p_x1, ln2s, ln2b, p_xn2);
    // y = gelu(xn2 @ w1 + b1)   [4096,1024]x[1024,2048]
    tgemm_kernel<2><<<dim3(2*DD/128, MM/128),256>>>(p_xn2, w1, p_y, MM, 2*DD, DD, b1, nullptr);
    // out = y @ w2 + b2 + x1    [4096,2048]x[2048,1024]
    tgemm_kernel<1><<<dim3(DD/128, MM/128),256>>>(p_y, w2, out, MM, DD, 2*DD, b2, p_x1);
}

// round 4
// speedup vs baseline: 3.1289x; 1.0363x over previous
#include <cuda_runtime.h>
#include <math.h>
#include <stdint.h>

#define BB 2
#define NSEQ 2048
#define DD 1024
#define NH 16
#define HS 64
#define MM (BB*NSEQ)   // 4096 rows

// ---------------- scratch (allocation-free, __device__ globals) ----------------
__device__ float g_xn [MM*DD];        // LN1 output (tf32-rounded)
__device__ float g_qkv[MM*3*DD];      // QKV (tf32-rounded)
__device__ float g_oh [MM*DD];        // attention head outputs (tf32-rounded)
__device__ float g_x1 [MM*DD];        // residual after attention (exact)
__device__ float g_xn2[MM*DD];        // LN2 output (tf32-rounded)
__device__ float g_y  [MM*2*DD];      // MLP hidden (tf32-rounded)
// tf32-rounded weight copies
__device__ float g_wqkv[DD*3*DD];
__device__ float g_wout[DD*DD];
__device__ float g_w1  [DD*2*DD];
__device__ float g_w2  [2*DD*DD];

__device__ __forceinline__ float gelu_tanh(float x){
    float u = 0.7978845608028654f * (x + 0.044715f*x*x*x);
    float t = 1.0f - 2.0f/(__expf(2.0f*u)+1.0f);
    return 0.5f*x*(1.0f+t);
}

__device__ __forceinline__ float tf32r(float x){
    uint32_t r;
    asm volatile("cvt.rna.tf32.f32 %0, %1;" : "=r"(r) : "f"(x));
    return __uint_as_float(r);
}

__device__ __forceinline__ void cp_async16(void* smem, const void* gmem){
    unsigned s = (unsigned)__cvta_generic_to_shared(smem);
    asm volatile("cp.async.cg.shared.global [%0], [%1], 16;" :: "r"(s), "l"(gmem));
}
__device__ __forceinline__ void cp_commit(){ asm volatile("cp.async.commit_group;"); }
template<int N> __device__ __forceinline__ void cp_wait(){ asm volatile("cp.async.wait_group %0;" :: "n"(N)); }

__device__ __forceinline__ void mma_tf32(float c[4], uint32_t a0, uint32_t a1,
                                         uint32_t a2, uint32_t a3,
                                         uint32_t b0, uint32_t b1){
    asm volatile(
        "mma.sync.aligned.m16n8k8.row.col.f32.tf32.tf32.f32 "
        "{%0,%1,%2,%3},{%4,%5,%6,%7},{%8,%9},{%0,%1,%2,%3};"
        : "+f"(c[0]), "+f"(c[1]), "+f"(c[2]), "+f"(c[3])
        : "r"(a0), "r"(a1), "r"(a2), "r"(a3), "r"(b0), "r"(b1));
}

// ---------------- tf32 rounding pass (weights) ----------------
__global__ __launch_bounds__(256) void round_kernel(const float* __restrict__ in,
                                                    float* __restrict__ out, int n4)
{
    const int i = blockIdx.x*256 + threadIdx.x;
    if (i < n4){
        float4 v = ((const float4*)in)[i];
        v.x = tf32r(v.x); v.y = tf32r(v.y); v.z = tf32r(v.z); v.w = tf32r(v.w);
        ((float4*)out)[i] = v;
    }
}

// ---------------- LayerNorm: one block per row, output tf32-rounded ----------------
__global__ __launch_bounds__(256) void ln_kernel(const float* __restrict__ x,
        const float* __restrict__ sc, const float* __restrict__ bi,
        float* __restrict__ out)
{
    const int row = blockIdx.x;
    const int t = threadIdx.x;
    const float4 v = ((const float4*)(x + (size_t)row*DD))[t];
    float s  = v.x+v.y+v.z+v.w;
    float sq = v.x*v.x+v.y*v.y+v.z*v.z+v.w*v.w;
    #pragma unroll
    for (int o=16;o>0;o>>=1){
        s  += __shfl_xor_sync(0xffffffffu,s ,o);
        sq += __shfl_xor_sync(0xffffffffu,sq,o);
    }
    __shared__ float ss[8], sqs[8];
    const int warp=t>>5, lane=t&31;
    if (lane==0){ ss[warp]=s; sqs[warp]=sq; }
    __syncthreads();
    if (t==0){
        float a=0.f,b=0.f;
        #pragma unroll
        for(int i=0;i<8;i++){a+=ss[i]; b+=sqs[i];}
        ss[0]=a; sqs[0]=b;
    }
    __syncthreads();
    const float mean = ss[0]*(1.0f/DD);
    const float var  = sqs[0]*(1.0f/DD) - mean*mean;
    const float inv  = rsqrtf(var + 1e-6f);
    const float4 sc4 = ((const float4*)sc)[t];
    const float4 bi4 = ((const float4*)bi)[t];
    float4 o4;
    o4.x = tf32r((v.x-mean)*inv*sc4.x + bi4.x);
    o4.y = tf32r((v.y-mean)*inv*sc4.y + bi4.y);
    o4.z = tf32r((v.z-mean)*inv*sc4.z + bi4.z);
    o4.w = tf32r((v.w-mean)*inv*sc4.w + bi4.w);
    ((float4*)(out + (size_t)row*DD))[t] = o4;
}

// ---------------- TF32 tensor-core GEMM 128x128x16, 256 threads ----------------
// Inputs A,B MUST be tf32-rounded already. No cvt in mainloop.
// EPI: 0 = C=tf32r(acc) ; 1 = C=acc+bias+res (exact) ; 2 = C=tf32r(gelu(acc+bias))
#define AS_STRIDE 20
#define BS_STRIDE 136
template<int EPI>
__global__ __launch_bounds__(256) void tgemm_kernel(
    const float* __restrict__ A, const float* __restrict__ B,
    float* __restrict__ C, int M, int N, int K,
    const float* __restrict__ bias, const float* __restrict__ res)
{
    __shared__ float As[2][128][AS_STRIDE];
    __shared__ float Bs[2][16][BS_STRIDE];

    const int tid  = threadIdx.x;
    const int lane = tid & 31;
    const int warp = tid >> 5;
    const int wm = warp >> 1;
    const int wn = warp & 1;
    const int mB = wm*32;
    const int nB = wn*64;
    const int bm = blockIdx.y*128;
    const int bn = blockIdx.x*128;

    const int ar  = tid >> 2;
    const int ac4 = (tid & 3) << 2;
    const int br  = tid >> 5;
    const int bc4 = (tid & 31) << 2;

    const float* Ag0 = A + (size_t)(bm + ar     )*K + ac4;
    const float* Ag1 = A + (size_t)(bm + ar + 64)*K + ac4;
    const float* Bg0 = B + (size_t)(br    )*N + bn + bc4;
    const float* Bg1 = B + (size_t)(br + 8)*N + bn + bc4;

    const int nk = K >> 4;

    cp_async16(&As[0][ar     ][ac4], Ag0);
    cp_async16(&As[0][ar + 64][ac4], Ag1);
    cp_async16(&Bs[0][br    ][bc4], Bg0);
    cp_async16(&Bs[0][br + 8][bc4], Bg1);
    cp_commit();

    float acc[2][8][4] = {};

    const int frow = lane >> 2;
    const int fcol = lane & 3;

    for (int kt = 0; kt < nk; kt++){
        const int cur = kt & 1;
        if (kt + 1 < nk){
            const int nxt = cur ^ 1;
            const int ko = (kt+1) << 4;
            cp_async16(&As[nxt][ar     ][ac4], Ag0 + ko);
            cp_async16(&As[nxt][ar + 64][ac4], Ag1 + ko);
            cp_async16(&Bs[nxt][br    ][bc4], Bg0 + (size_t)ko*N);
            cp_async16(&Bs[nxt][br + 8][bc4], Bg1 + (size_t)ko*N);
            cp_commit();
            cp_wait<1>();
        } else {
            cp_wait<0>();
        }
        __syncthreads();

        #pragma unroll
        for (int kk = 0; kk < 2; kk++){
            const int kc = kk*8 + fcol;
            uint32_t af[2][4], bf[8][2];
            #pragma unroll
            for (int i = 0; i < 2; i++){
                const int r0 = mB + i*16 + frow;
                af[i][0] = __float_as_uint(As[cur][r0    ][kc    ]);
                af[i][1] = __float_as_uint(As[cur][r0 + 8][kc    ]);
                af[i][2] = __float_as_uint(As[cur][r0    ][kc + 4]);
                af[i][3] = __float_as_uint(As[cur][r0 + 8][kc + 4]);
            }
            #pragma unroll
            for (int j = 0; j < 8; j++){
                const int n = nB + j*8 + frow;
                bf[j][0] = __float_as_uint(Bs[cur][kk*8 + fcol    ][n]);
                bf[j][1] = __float_as_uint(Bs[cur][kk*8 + fcol + 4][n]);
            }
            #pragma unroll
            for (int i = 0; i < 2; i++)
                #pragma unroll
                for (int j = 0; j < 8; j++)
                    mma_tf32(acc[i][j], af[i][0], af[i][1], af[i][2], af[i][3],
                             bf[j][0], bf[j][1]);
        }
        __syncthreads();
    }

    #pragma unroll
    for (int i = 0; i < 2; i++){
        const int row = bm + mB + i*16 + frow;
        #pragma unroll
        for (int j = 0; j < 8; j++){
            const int col = bn + nB + j*8 + fcol*2;
            float v0 = acc[i][j][0], v1 = acc[i][j][1];
            float v2 = acc[i][j][2], v3 = acc[i][j][3];
            const size_t o0 = (size_t)row*N + col;
            const size_t o1 = (size_t)(row+8)*N + col;
            if (EPI == 0){
                v0 = tf32r(v0); v1 = tf32r(v1); v2 = tf32r(v2); v3 = tf32r(v3);
            } else if (EPI == 1){
                const float b0 = bias[col], b1 = bias[col+1];
                v0 += b0 + res[o0];   v1 += b1 + res[o0+1];
                v2 += b0 + res[o1];   v3 += b1 + res[o1+1];
            } else if (EPI == 2){
                const float b0 = bias[col], b1 = bias[col+1];
                v0 = tf32r(gelu_tanh(v0 + b0)); v1 = tf32r(gelu_tanh(v1 + b1));
                v2 = tf32r(gelu_tanh(v2 + b0)); v3 = tf32r(gelu_tanh(v3 + b1));
            }
            *(float2*)(C + o0) = make_float2(v0, v1);
            *(float2*)(C + o1) = make_float2(v2, v3);
        }
    }
}

// ---------------- Causal flash attention on tensor cores (tf32) ----------------
// qkv is tf32-rounded at production; raw bit loads, no in-loop cvt.
#define ATS 68
__global__ __launch_bounds__(128, 3) void attn_tc_kernel(const float* __restrict__ qkv,
                                                         float* __restrict__ oh)
{
    extern __shared__ float sm[];
    float* Qs = sm;                 // [64][ATS]  Q[row][d]
    float* KP = sm + 64*ATS;        // [64][ATS]  K[key][d], then P[row][key]
    float* Vt = sm + 2*64*ATS;      // [64][ATS]  V^T[d][key]

    const int qt = gridDim.x - 1 - blockIdx.x;
    const int bh = blockIdx.y;
    const int b = bh >> 4;
    const int h = bh & 15;
    const int tid = threadIdx.x;
    const int lane = tid & 31;
    const int warp = tid >> 5;
    const int mB = warp * 16;
    const int g = lane >> 2;
    const int c = lane & 3;
    const size_t base = (size_t)b * NSEQ * (3*DD);
    const int hoff = h * HS;

    for (int i = tid; i < 64*16; i += 128){
        const int row = i >> 4, d4 = (i & 15) << 2;
        const float4 q4 = *(const float4*)(qkv + base + (size_t)(qt*64+row)*(3*DD) + hoff + d4);
        *(float4*)&Qs[row*ATS + d4] = q4;
    }
    __syncthreads();

    uint32_t qa[8][4];
    #pragma unroll
    for (int kk = 0; kk < 8; kk++){
        qa[kk][0] = __float_as_uint(Qs[(mB+g  )*ATS + kk*8 + c    ]);
        qa[kk][1] = __float_as_uint(Qs[(mB+g+8)*ATS + kk*8 + c    ]);
        qa[kk][2] = __float_as_uint(Qs[(mB+g  )*ATS + kk*8 + c + 4]);
        qa[kk][3] = __float_as_uint(Qs[(mB+g+8)*ATS + kk*8 + c + 4]);
    }

    float o[8][4] = {};
    float m0=-1e30f, m1=-1e30f, l0=0.f, l1=0.f;

    const int r0g = qt*64 + mB + g;
    const int r1g = r0g + 8;

    for (int jt = 0; jt <= qt; jt++){
        __syncthreads();
        for (int i = tid; i < 64*16; i += 128){
            const int row = i >> 4, d4 = (i & 15) << 2;
            const size_t roff = base + (size_t)(jt*64+row)*(3*DD) + hoff + d4;
            const float4 k4 = *(const float4*)(qkv + roff + DD);
            *(float4*)&KP[row*ATS + d4] = k4;
            const float4 v4 = *(const float4*)(qkv + roff + 2*DD);
            Vt[(d4+0)*ATS+row]=v4.x; Vt[(d4+1)*ATS+row]=v4.y;
            Vt[(d4+2)*ATS+row]=v4.z; Vt[(d4+3)*ATS+row]=v4.w;
        }
        __syncthreads();

        float s[8][4] = {};
        #pragma unroll
        for (int kk = 0; kk < 8; kk++){
            #pragma unroll
            for (int j = 0; j < 8; j++){
                const uint32_t b0 = __float_as_uint(KP[(j*8+g)*ATS + kk*8 + c    ]);
                const uint32_t b1 = __float_as_uint(KP[(j*8+g)*ATS + kk*8 + c + 4]);
                mma_tf32(s[j], qa[kk][0], qa[kk][1], qa[kk][2], qa[kk][3], b0, b1);
            }
        }
        __syncthreads();

        float rm0 = -1e30f, rm1 = -1e30f;
        #pragma unroll
        for (int j = 0; j < 8; j++){
            const int col = jt*64 + j*8 + 2*c;
            #pragma unroll
            for (int t2 = 0; t2 < 2; t2++){
                float v0 = s[j][t2]*0.125f;
                float v1 = s[j][2+t2]*0.125f;
                if (jt == qt){
                    if (col+t2 > r0g) v0 = -1e30f;
                    if (col+t2 > r1g) v1 = -1e30f;
                }
                s[j][t2] = v0;  s[j][2+t2] = v1;
                rm0 = fmaxf(rm0, v0); rm1 = fmaxf(rm1, v1);
            }
        }
        #pragma unroll
        for (int off = 1; off <= 2; off <<= 1){
            rm0 = fmaxf(rm0, __shfl_xor_sync(0xffffffffu, rm0, off));
            rm1 = fmaxf(rm1, __shfl_xor_sync(0xffffffffu, rm1, off));
        }
        const float mn0 = fmaxf(m0, rm0), mn1 = fmaxf(m1, rm1);
        const float alpha0 = __expf(m0 - mn0), alpha1 = __expf(m1 - mn1);
        m0 = mn0; m1 = mn1;

        float rs0 = 0.f, rs1 = 0.f;
        #pragma unroll
        for (int j = 0; j < 8; j++){
            float p0 = __expf(s[j][0] - mn0);
            float p1 = __expf(s[j][1] - mn0);
            float p2 = __expf(s[j][2] - mn1);
            float p3 = __expf(s[j][3] - mn1);
            rs0 += p0 + p1;  rs1 += p2 + p3;
            *(float2*)&KP[(mB+g  )*ATS + j*8 + 2*c] = make_float2(tf32r(p0), tf32r(p1));
            *(float2*)&KP[(mB+g+8)*ATS + j*8 + 2*c] = make_float2(tf32r(p2), tf32r(p3));
        }
        #pragma unroll
        for (int off = 1; off <= 2; off <<= 1){
            rs0 += __shfl_xor_sync(0xffffffffu, rs0, off);
            rs1 += __shfl_xor_sync(0xffffffffu, rs1, off);
        }
        l0 = l0*alpha0 + rs0;
        l1 = l1*alpha1 + rs1;

        #pragma unroll
        for (int j = 0; j < 8; j++){
            o[j][0] *= alpha0; o[j][1] *= alpha0;
            o[j][2] *= alpha1; o[j][3] *= alpha1;
        }
        __syncwarp();

        #pragma unroll
        for (int kk = 0; kk < 8; kk++){
            const uint32_t a0 = __float_as_uint(KP[(mB+g  )*ATS + kk*8 + c    ]);
            const uint32_t a1 = __float_as_uint(KP[(mB+g+8)*ATS + kk*8 + c    ]);
            const uint32_t a2 = __float_as_uint(KP[(mB+g  )*ATS + kk*8 + c + 4]);
            const uint32_t a3 = __float_as_uint(KP[(mB+g+8)*ATS + kk*8 + c + 4]);
            #pragma unroll
            for (int j = 0; j < 8; j++){
                const uint32_t b0 = __float_as_uint(Vt[(j*8+g)*ATS + kk*8 + c    ]);
                const uint32_t b1 = __float_as_uint(Vt[(j*8+g)*ATS + kk*8 + c + 4]);
                mma_tf32(o[j], a0, a1, a2, a3, b0, b1);
            }
        }
    }

    // normalize + write (tf32-rounded: feeds out-proj GEMM A operand)
    const float inv0 = 1.0f/l0, inv1 = 1.0f/l1;
    #pragma unroll
    for (int j = 0; j < 8; j++){
        const int col = hoff + j*8 + 2*c;
        float* p0 = oh + (size_t)(b*NSEQ + r0g)*DD + col;
        float* p1 = oh + (size_t)(b*NSEQ + r1g)*DD + col;
        *(float2*)p0 = make_float2(tf32r(o[j][0]*inv0), tf32r(o[j][1]*inv0));
        *(float2*)p1 = make_float2(tf32r(o[j][2]*inv1), tf32r(o[j][3]*inv1));
    }
}

// ---------------- launch ----------------
extern "C" void kernel_launch(void* const* d_in, const int* in_sizes, int n_in,
                              void* d_out, int out_size)
{
    const float* x    = (const float*)d_in[0];
    const float* ln1s = (const float*)d_in[1];
    const float* ln1b = (const float*)d_in[2];
    const float* wqkv = (const float*)d_in[3];
    const float* wout = (const float*)d_in[4];
    const float* bout = (const float*)d_in[5];
    const float* ln2s = (const float*)d_in[6];
    const float* ln2b = (const float*)d_in[7];
    const float* w1   = (const float*)d_in[8];
    const float* b1   = (const float*)d_in[9];
    const float* w2   = (const float*)d_in[10];
    const float* b2   = (const float*)d_in[11];
    float* out = (float*)d_out;

    float *p_xn,*p_qkv,*p_oh,*p_x1,*p_xn2,*p_y;
    float *p_wqkv,*p_wout,*p_w1,*p_w2;
    cudaGetSymbolAddress((void**)&p_xn , g_xn );
    cudaGetSymbolAddress((void**)&p_qkv, g_qkv);
    cudaGetSymbolAddress((void**)&p_oh , g_oh );
    cudaGetSymbolAddress((void**)&p_x1 , g_x1 );
    cudaGetSymbolAddress((void**)&p_xn2, g_xn2);
    cudaGetSymbolAddress((void**)&p_y  , g_y  );
    cudaGetSymbolAddress((void**)&p_wqkv, g_wqkv);
    cudaGetSymbolAddress((void**)&p_wout, g_wout);
    cudaGetSymbolAddress((void**)&p_w1  , g_w1  );
    cudaGetSymbolAddress((void**)&p_w2  , g_w2  );

    const int attn_smem = 3*64*ATS*sizeof(float);
    cudaFuncSetAttribute(attn_tc_kernel, cudaFuncAttributeMaxDynamicSharedMemorySize, attn_smem);

    // round weights to tf32 (graph-capturable, deterministic)
    round_kernel<<<(DD*3*DD/4+255)/256,256>>>(wqkv, p_wqkv, DD*3*DD/4);
    round_kernel<<<(DD*DD/4+255)/256,256>>>(wout, p_wout, DD*DD/4);
    round_kernel<<<(DD*2*DD/4+255)/256,256>>>(w1, p_w1, DD*2*DD/4);
    round_kernel<<<(2*DD*DD/4+255)/256,256>>>(w2, p_w2, 2*DD*DD/4);

    // LN1 (rounded output)
    ln_kernel<<<MM,256>>>(x, ln1s, ln1b, p_xn);
    // QKV = xn @ w_qkv (rounded output)
    tgemm_kernel<0><<<dim3(3*DD/128, MM/128),256>>>(p_xn, p_wqkv, p_qkv, MM, 3*DD, DD, nullptr, nullptr);
    // causal attention (tensor cores; rounded output)
    attn_tc_kernel<<<dim3(NSEQ/64, BB*NH),128,attn_smem>>>(p_qkv, p_oh);
    // x1 = oh @ w_out + b_out + x (exact)
    tgemm_kernel<1><<<dim3(DD/128, MM/128),256>>>(p_oh, p_wout, p_x1, MM, DD, DD, bout, x);
    // LN2 (rounded output)
    ln_kernel<<<MM,256>>>(p_x1, ln2s, ln2b, p_xn2);
    // y = gelu(xn2 @ w1 + b1) (rounded output)
    tgemm_kernel<2><<<dim3(2*DD/128, MM/128),256>>>(p_xn2, p_w1, p_y, MM, 2*DD, DD, b1, nullptr);
    // out = y @ w2 + b2 + x1 (exact)
    tgemm_kernel<1><<<dim3(DD/128, MM/128),256>>>(p_y, p_w2, out, MM, DD, 2*DD, b2, p_x1);
}